// round 9
// baseline (speedup 1.0000x reference)
#include <cuda_runtime.h>
#include <math.h>

#define BB   2
#define NN   1024
#define DIMM 2048
#define HH   16
#define DHH  128
#define TT   (BB*NN)    // 2048 tokens
#define HD   (HH*DHH)   // 2048
#define MAXP 16
#define NEGV -1e30f
#define QKVG_LD 8192

#define STAGES 3
#define ASTR   36                  // smem row stride (floats)
#define STAGE  (128*ASTR)          // 4608 floats per tile per stage
#define SMEM_BYTES (STAGES*2*STAGE*4)   // 110592 B

#define SCORE_SMEM (16*1025*4)     // 65600 B

// ---------------- scratch (device globals; zero-init, no allocs) ----------------
__device__ __align__(256) float g_qkvg[TT*QKVG_LD];    // cols: q[0:2048) k[2048:4096) v[4096:6144) vg[6144:8192)
__device__ __align__(256) float g_vt[TT*HD];           // V transposed per batch: [b][c][n]
__device__ __align__(256) float g_sim [BB*HH*NN*NN];   // raw scores (QK output)
__device__ __align__(256) float g_sim2[BB*HH*NN*NN];   // mixed attn (score_fused output)
__device__ __align__(256) float g_logits[BB*HH*NN*MAXP];
__device__ __align__(256) float g_outh[BB*HH*NN*DHH];
__device__ __align__(256) float g_hg[TT*HH];
__device__ __align__(256) float g_gated[TT*HD];
__device__ __align__(256) float g_cos[NN*DHH];
__device__ __align__(256) float g_sin[NN*DHH];
__device__ __align__(256) float g_xr[TT*DIMM];         // x rounded to tf32
__device__ __align__(256) float g_wcatT[4*DIMM*HD];    // [8192][2048]: wqT|wkT|wvT|wvgT
__device__ __align__(256) float g_woutT[HD*DIMM];

__device__ __forceinline__ float sigmoidf_(float x) { return 1.0f / (1.0f + expf(-x)); }

__device__ __forceinline__ unsigned f2tf(float x) {
    unsigned u; asm("cvt.rna.tf32.f32 %0, %1;" : "=r"(u) : "f"(x)); return u;
}
__device__ __forceinline__ float tf32r(float x) { return __uint_as_float(f2tf(x)); }

__device__ __forceinline__ void cpa16(float* dst, const float* src) {
    unsigned d = (unsigned)__cvta_generic_to_shared(dst);
    asm volatile("cp.async.cg.shared.global [%0], [%1], 16;" :: "r"(d), "l"(src));
}
__device__ __forceinline__ void cpa4(float* dst, const float* src) {
    unsigned d = (unsigned)__cvta_generic_to_shared(dst);
    asm volatile("cp.async.ca.shared.global [%0], [%1], 4;" :: "r"(d), "l"(src));
}

__device__ __forceinline__ void ldsm4(unsigned& r0, unsigned& r1, unsigned& r2, unsigned& r3,
                                      const float* p) {
    unsigned a = (unsigned)__cvta_generic_to_shared(p);
    asm volatile("ldmatrix.sync.aligned.m8n8.x4.shared.b16 {%0,%1,%2,%3}, [%4];"
                 : "=r"(r0), "=r"(r1), "=r"(r2), "=r"(r3) : "r"(a));
}

#define MMA_TF32(cc, aa, bb)                                                     \
    asm volatile("mma.sync.aligned.m16n8k8.row.col.f32.tf32.tf32.f32 "           \
                 "{%0,%1,%2,%3},{%4,%5,%6,%7},{%8,%9},{%0,%1,%2,%3};"            \
                 : "+f"((cc)[0]), "+f"((cc)[1]), "+f"((cc)[2]), "+f"((cc)[3])    \
                 : "r"((aa)[0]), "r"((aa)[1]), "r"((aa)[2]), "r"((aa)[3]),       \
                   "r"((bb)[0]), "r"((bb)[1]))

// =====================================================================
// tf32 tensor-core GEMM. Operands MUST be pre-rounded to tf32 in gmem.
//   C[M,N] = scale * A[M,K] @ B^T  where B is stored [N][K] row-major.
// flags: 2 = causal block skip; 4 = triangular K bound (kmax=row0+128,
//        A upper band must be zero); 8 = sigmoid(acc+bias[col]) epilogue;
//        16 = sigmoid(acc+bias[col-6144]) only for col0 >= 6144.
// =====================================================================
__global__ __launch_bounds__(256, 2) void gemm_tc(
    const float* __restrict__ A, int lda, long long sAb, long long sAh,
    const float* __restrict__ B, int ldb, long long sBb, long long sBh,
    float* __restrict__ C, int ldc, long long sCb, long long sCh,
    int K, int flags, const float* __restrict__ bias, float scale)
{
    if ((flags & 2) && blockIdx.x > blockIdx.y) return;
    int z = blockIdx.z, bz = z >> 4, hz = z & 15;
    const float* Ab = A + bz * sAb + hz * sAh;
    const float* Bb = B + bz * sBb + hz * sBh;
    float*       Cb = C + bz * sCb + hz * sCh;

    extern __shared__ float sm[];
    float* Asm = sm;
    float* Bsm = sm + STAGES * STAGE;

    const int tid = threadIdx.x, lane = tid & 31, wid = tid >> 5;
    const int wm = wid >> 2, wn = wid & 3;
    const int g = lane >> 2, tg = lane & 3;
    const int row0 = blockIdx.y * 128, col0 = blockIdx.x * 128;

    float c[4][4][4];
#pragma unroll
    for (int mt = 0; mt < 4; mt++)
#pragma unroll
        for (int nt = 0; nt < 4; nt++)
#pragma unroll
            for (int e = 0; e < 4; e++) c[mt][nt][e] = 0.f;

    int kmax = K;
    if (flags & 4) { int t = row0 + 128; if (t < kmax) kmax = t; }
    const int niter = kmax >> 5;

    const int a_rl = (lane & 7) + ((lane >> 3) & 1) * 8;
    const int a_ko = (lane >> 4) * 4;
    const int b_rl = (lane & 7) + ((lane >> 4) & 1) * 8;
    const int b_ko = ((lane >> 3) & 1) * 4;
    const float* aF[4]; const float* bF[2];
#pragma unroll
    for (int mt = 0; mt < 4; mt++)
        aF[mt] = Asm + (wm * 64 + mt * 16 + a_rl) * ASTR + a_ko;
#pragma unroll
    for (int p = 0; p < 2; p++)
        bF[p] = Bsm + (wn * 32 + p * 16 + b_rl) * ASTR + b_ko;

    auto load_stage = [&](int s, int k0) {
        float* as = Asm + s * STAGE;
        float* bs = Bsm + s * STAGE;
#pragma unroll
        for (int i = 0; i < 4; i++) {
            int chunk = i * 256 + tid;
            int r = chunk >> 3, seg = (chunk & 7) << 2;
            cpa16(as + r * ASTR + seg, Ab + (size_t)(row0 + r) * lda + k0 + seg);
            cpa16(bs + r * ASTR + seg, Bb + (size_t)(col0 + r) * ldb + k0 + seg);
        }
    };

    auto compute_stage = [&](int s) {
        const int off = s * STAGE;
#pragma unroll
        for (int ks = 0; ks < 4; ks++) {
            const int kb = ks * 8;
            unsigned a[4][4], b[4][2];
#pragma unroll
            for (int mt = 0; mt < 4; mt++)
                ldsm4(a[mt][0], a[mt][1], a[mt][2], a[mt][3], aF[mt] + off + kb);
#pragma unroll
            for (int p = 0; p < 2; p++) {
                unsigned t0, t1, t2, t3;
                ldsm4(t0, t1, t2, t3, bF[p] + off + kb);
                b[2 * p][0] = t0; b[2 * p][1] = t1;
                b[2 * p + 1][0] = t2; b[2 * p + 1][1] = t3;
            }
#pragma unroll
            for (int mt = 0; mt < 4; mt++)
#pragma unroll
                for (int nt = 0; nt < 4; nt++)
                    MMA_TF32(c[mt][nt], a[mt], b[nt]);
        }
    };

#pragma unroll
    for (int s = 0; s < STAGES - 1; s++) {
        if (s < niter) load_stage(s, s * 32);
        asm volatile("cp.async.commit_group;");
    }
    for (int it = 0; it < niter; it++) {
        asm volatile("cp.async.wait_group %0;" :: "n"(STAGES - 2));
        __syncthreads();
        int nxt = it + STAGES - 1;
        if (nxt < niter) load_stage(nxt % STAGES, nxt * 32);
        asm volatile("cp.async.commit_group;");
        compute_stage(it % STAGES);
    }

    const bool sg = ((flags & 8) != 0) || ((flags & 16) && col0 >= 6144);
    const int boff = (flags & 16) ? 6144 : 0;
#pragma unroll
    for (int mt = 0; mt < 4; mt++) {
        int r0 = row0 + wm * 64 + mt * 16 + g;
#pragma unroll
        for (int nt = 0; nt < 4; nt++) {
            int col = col0 + wn * 32 + nt * 8 + 2 * tg;
            float v0 = c[mt][nt][0] * scale, v1 = c[mt][nt][1] * scale;
            float v2 = c[mt][nt][2] * scale, v3 = c[mt][nt][3] * scale;
            if (sg) {
                float b0 = bias[col - boff], b1 = bias[col + 1 - boff];
                v0 = sigmoidf_(v0 + b0);  v1 = sigmoidf_(v1 + b1);
                v2 = sigmoidf_(v2 + b0);  v3 = sigmoidf_(v3 + b1);
            }
            float2 p0; p0.x = v0; p0.y = v1;
            float2 p1; p1.x = v2; p1.y = v3;
            *(float2*)(Cb + (size_t)r0 * ldc + col)       = p0;
            *(float2*)(Cb + (size_t)(r0 + 8) * ldc + col) = p1;
        }
    }
}

// ---------------- transpose + tf32 round: out[c][r] = tf32(in[r][c]) ----------------
__global__ void transpose_round(const float* __restrict__ in, float* __restrict__ out,
                                int rows, int cols, int ldin,
                                long long inz, long long outz) {
    __shared__ float t[32][33];
    const float* ip = in + blockIdx.z * inz;
    float* op = out + blockIdx.z * outz;
    int c0 = blockIdx.x * 32, r0 = blockIdx.y * 32;
    int tx = threadIdx.x, ty = threadIdx.y;   // 32 x 8
#pragma unroll
    for (int i = 0; i < 32; i += 8)
        t[ty + i][tx] = ip[(size_t)(r0 + ty + i) * ldin + c0 + tx];
    __syncthreads();
#pragma unroll
    for (int i = 0; i < 32; i += 8)
        op[(size_t)(c0 + ty + i) * rows + r0 + tx] = tf32r(t[tx][ty + i]);
}

// ---------------- tf32 round copy (x -> g_xr) ----------------
__global__ void round_copy(const float* __restrict__ in, float* __restrict__ out) {
    int i = (blockIdx.x * 256 + threadIdx.x) * 4;
    float4 v = *(const float4*)(in + i);
    v.x = tf32r(v.x); v.y = tf32r(v.y); v.z = tf32r(v.z); v.w = tf32r(v.w);
    *(float4*)(out + i) = v;
}

// ---------------- rope table ----------------
__global__ void rope_cs_kernel(const float* __restrict__ rf) {
    int idx = blockIdx.x * 256 + threadIdx.x;
    float f = rf[idx];
    g_cos[idx] = cosf(f);
    g_sin[idx] = sinf(f);
}

// ---------------- warp-per-vector L2-norm + rotary (+ CoPE logits for q) ----------
// q/k live in g_qkvg (ld 8192); stores tf32-rounded; logits full precision.
__global__ void norm_rot2_kernel(const float* __restrict__ cope) {
    int lane = threadIdx.x & 31;
    int w = blockIdx.x * 8 + (threadIdx.x >> 5);
    const int NV = TT * HH;
    int isK = (w >= NV) ? 1 : 0;
    int vec = isK ? (w - NV) : w;
    int token = vec >> 4, h = vec & 15;
    int n = token & (NN - 1), b = token >> 10;

    float* ptr = g_qkvg + (size_t)token * QKVG_LD + isK * 2048 + h * DHH + lane * 4;
    float4 v = *(float4*)ptr;
    float ss = v.x * v.x + v.y * v.y + v.z * v.z + v.w * v.w;
#pragma unroll
    for (int o = 16; o > 0; o >>= 1) ss += __shfl_xor_sync(0xffffffffu, ss, o);
    float inv = 1.0f / fmaxf(sqrtf(ss), 1e-12f);
    v.x *= inv; v.y *= inv; v.z *= inv; v.w *= inv;

    float4 cs = *(const float4*)(g_cos + n * DHH + lane * 4);
    float4 sn = *(const float4*)(g_sin + n * DHH + lane * 4);
    float4 o;
    o.x = v.x * cs.x - v.y * sn.x;
    o.y = v.y * cs.y + v.x * sn.y;
    o.z = v.z * cs.z - v.w * sn.z;
    o.w = v.w * cs.w + v.z * sn.w;
    float4 orr;
    orr.x = tf32r(o.x); orr.y = tf32r(o.y); orr.z = tf32r(o.z); orr.w = tf32r(o.w);
    *(float4*)ptr = orr;

    if (!isK) {
        float myv = 0.f;
#pragma unroll
        for (int p = 0; p < MAXP; p++) {
            float4 cp = *(const float4*)(cope + p * DHH + lane * 4);
            float pa = o.x * cp.x + o.y * cp.y + o.z * cp.z + o.w * cp.w;
#pragma unroll
            for (int off = 16; off > 0; off >>= 1)
                pa += __shfl_xor_sync(0xffffffffu, pa, off);
            if (lane == p) myv = pa;
        }
        if (lane < MAXP)
            g_logits[((size_t)(b * HH + h) * NN + n) * MAXP + lane] = myv;
    }
}

// =====================================================================
// Fused: pre-mix talking heads + CoPE + softmax + post-mix talking heads.
// grid (NN, BB), 256 threads, 65.6 KB dyn smem (16 head-rows, pad 1025).
// Reads g_sim (raw scores, only j<=i valid) + g_logits; writes g_sim2
// (tf32-rounded mixed attn, j<=i only; upper band stays zero for AV).
// Thread t owns columns j = t, t+256, t+512, t+768 (conflict-free).
// =====================================================================
__global__ __launch_bounds__(256) void score_fused(const float* __restrict__ thp,
                                                   const float* __restrict__ tho) {
    extern __shared__ float sbuf[];   // [16][1025]
    __shared__ float sth_pre[256], sth_post[256], lrow[256];
    __shared__ float spart[32], soff[32], sred[8];
    __shared__ float s_tot, s_scal;

    const int i = blockIdx.x, b = blockIdx.y;
    const int tid = threadIdx.x, lane = tid & 31, w = tid >> 5;

    sth_pre[tid] = thp[tid];
    sth_post[tid] = tho[tid];
    {   int h = tid >> 4, p = tid & 15;
        lrow[tid] = g_logits[(((size_t)(b * HH + h)) * NN + i) * MAXP + p]; }

    const int len = ((i + 1) + 3) & ~3;
    for (int g = 0; g < 16; g++) {
        const float* src = g_sim + (((size_t)(b * HH + g)) * NN + i) * NN;
        for (int j = tid; j < len; j += 256) cpa4(&sbuf[g * 1025 + j], src + j);
    }
    asm volatile("cp.async.commit_group;");
    asm volatile("cp.async.wait_group 0;");
    __syncthreads();

    // ---- pre-mix in place (column-exclusive, no hazard) ----
#pragma unroll
    for (int c = 0; c < 4; c++) {
        int j = c * 256 + tid;
        if (j <= i) {
            float vals[16], outv[16];
#pragma unroll
            for (int g = 0; g < 16; g++) vals[g] = sbuf[g * 1025 + j];
#pragma unroll
            for (int h = 0; h < 16; h++) {
                float s = 0.f;
#pragma unroll
                for (int g = 0; g < 16; g++) s = fmaf(sth_pre[h * 16 + g], vals[g], s);
                outv[h] = s;
            }
#pragma unroll
            for (int h = 0; h < 16; h++) sbuf[h * 1025 + j] = outv[h];
        }
    }
    __syncthreads();

    float acc[16][4];
#pragma unroll
    for (int h = 0; h < 16; h++)
#pragma unroll
        for (int c = 0; c < 4; c++) acc[h][c] = 0.f;

    for (int hd = 0; hd < 16; hd++) {
        float v[4], gate[4], inc[4];
#pragma unroll
        for (int c = 0; c < 4; c++) {
            int j = c * 256 + tid;
            v[c] = sbuf[hd * 1025 + j];
            gate[c] = (j <= i) ? sigmoidf_(v[c]) : 0.f;
            float s = gate[c];
#pragma unroll
            for (int o = 1; o < 32; o <<= 1) {
                float t = __shfl_up_sync(0xffffffffu, s, o);
                if (lane >= o) s += t;
            }
            inc[c] = s;
        }
        if (lane == 31) {
            spart[w] = inc[0];      spart[8 + w] = inc[1];
            spart[16 + w] = inc[2]; spart[24 + w] = inc[3];
        }
        __syncthreads();
        if (tid < 32) {
            float x = spart[tid], s = x;
#pragma unroll
            for (int o = 1; o < 32; o <<= 1) {
                float t = __shfl_up_sync(0xffffffffu, s, o);
                if (tid >= o) s += t;
            }
            soff[tid] = s - x;
            if (tid == 31) s_tot = s;
        }
        __syncthreads();
        float total = s_tot;
        float nv[4];
#pragma unroll
        for (int c = 0; c < 4; c++) {
            int j = c * 256 + tid;
            if (j <= i) {
                float excl = soff[c * 8 + w] + (inc[c] - gate[c]);
                float pos = total - excl;             // inclusive reverse cumsum
                pos = fminf(fmaxf(pos, 0.f), 15.0f);
                float pf = floorf(pos);
                float wi = pos - pf;
                int fi = (int)pf, ci = (int)ceilf(pos);
                nv[c] = v[c] + lrow[hd * 16 + ci] * wi + lrow[hd * 16 + fi] * (1.0f - wi);
            } else nv[c] = NEGV;
        }
        float m = fmaxf(fmaxf(nv[0], nv[1]), fmaxf(nv[2], nv[3]));
#pragma unroll
        for (int o = 16; o > 0; o >>= 1) m = fmaxf(m, __shfl_xor_sync(0xffffffffu, m, o));
        if (lane == 0) sred[w] = m;
        __syncthreads();
        if (tid == 0) {
            float mm = sred[0];
            for (int k = 1; k < 8; k++) mm = fmaxf(mm, sred[k]);
            s_scal = mm;
        }
        __syncthreads();
        m = s_scal;
        float e[4], ls = 0.f;
#pragma unroll
        for (int c = 0; c < 4; c++) { e[c] = expf(nv[c] - m); ls += e[c]; }
#pragma unroll
        for (int o = 16; o > 0; o >>= 1) ls += __shfl_xor_sync(0xffffffffu, ls, o);
        if (lane == 0) sred[w] = ls;
        __syncthreads();
        if (tid == 0) {
            float t = 0.f;
            for (int k = 0; k < 8; k++) t += sred[k];
            s_scal = t;
        }
        __syncthreads();
        float invs = 1.0f / s_scal;
        float attn[4];
#pragma unroll
        for (int c = 0; c < 4; c++) attn[c] = e[c] * invs;
#pragma unroll
        for (int h = 0; h < 16; h++) {
            float t = sth_post[h * 16 + hd];
#pragma unroll
            for (int c = 0; c < 4; c++) acc[h][c] = fmaf(t, attn[c], acc[h][c]);
        }
    }

    // ---- write mixed attn (tf32), j <= i only ----
#pragma unroll
    for (int h = 0; h < 16; h++) {
        float* dst = g_sim2 + (((size_t)(b * HH + h)) * NN + i) * NN;
#pragma unroll
        for (int c = 0; c < 4; c++) {
            int j = c * 256 + tid;
            if (j <= i) dst[j] = tf32r(acc[h][c]);
        }
    }
}

// ---------------- head gate ----------------
__global__ void hgate_kernel(const float* __restrict__ x, const float* __restrict__ wh,
                             const float* __restrict__ bh) {
    int token = blockIdx.x;
    __shared__ __align__(16) float sx[DIMM];
    int tid = threadIdx.x;
    *(float4*)&sx[tid * 4] = *(const float4*)&x[(size_t)token * DIMM + tid * 4];
    __syncthreads();
    int h = tid >> 5, lane = tid & 31;
    float s = 0.f;
    for (int e = lane; e < DIMM; e += 32) s = fmaf(sx[e], wh[e * HH + h], s);
#pragma unroll
    for (int o = 16; o > 0; o >>= 1) s += __shfl_xor_sync(0xffffffffu, s, o);
    if (lane == 0) g_hg[token * HH + h] = sigmoidf_(s + bh[h]);
}

// ---------------- apply gates, merge heads (tf32-rounded output) ----------------
__global__ void gate_mul_kernel() {
    int idx = blockIdx.x * 256 + threadIdx.x;
    int token = idx >> 11;
    int c = idx & 2047;
    int h = c >> 7, d = c & 127;
    int b = token >> 10, n = token & 1023;
    float o = g_outh[(((size_t)(b * HH + h)) * NN + n) * DHH + d];
    float vg = g_qkvg[(size_t)token * QKVG_LD + 6144 + c];
    g_gated[idx] = tf32r(o * g_hg[token * HH + h] * vg);
}

// ---------------- launch ----------------
extern "C" void kernel_launch(void* const* d_in, const int* in_sizes, int n_in,
                              void* d_out, int out_size) {
    const float* x    = (const float*)d_in[0];
    const float* rf   = (const float*)d_in[1];
    const float* wq   = (const float*)d_in[2];
    const float* wk   = (const float*)d_in[3];
    const float* wv   = (const float*)d_in[4];
    const float* cope = (const float*)d_in[5];
    const float* thp  = (const float*)d_in[6];
    const float* tho  = (const float*)d_in[7];
    const float* wvg  = (const float*)d_in[8];
    const float* bvg  = (const float*)d_in[9];
    const float* whg  = (const float*)d_in[10];
    const float* bhg  = (const float*)d_in[11];
    const float* wout = (const float*)d_in[12];
    float* out = (float*)d_out;

    cudaFuncSetAttribute(gemm_tc, cudaFuncAttributeMaxDynamicSharedMemorySize, SMEM_BYTES);
    cudaFuncSetAttribute(score_fused, cudaFuncAttributeMaxDynamicSharedMemorySize, SCORE_SMEM);

    void *pqkvg, *pvt, *psim, *psim2, *pouth, *pgated, *pxr, *pwcat, *pwoutT;
    cudaGetSymbolAddress(&pqkvg, g_qkvg);
    cudaGetSymbolAddress(&pvt, g_vt);
    cudaGetSymbolAddress(&psim, g_sim);
    cudaGetSymbolAddress(&psim2, g_sim2);
    cudaGetSymbolAddress(&pouth, g_outh);
    cudaGetSymbolAddress(&pgated, g_gated);
    cudaGetSymbolAddress(&pxr, g_xr);
    cudaGetSymbolAddress(&pwcat, g_wcatT);
    cudaGetSymbolAddress(&pwoutT, g_woutT);

    float* qkvg = (float*)pqkvg;
    float* wcat = (float*)pwcat;

    dim3 tBlk(32, 8);
    dim3 tGrd(64, 64, 1);

    rope_cs_kernel<<<NN * DHH / 256, 256>>>(rf);

    // pre-pass: transpose+round weights into concatenated [8192][2048] + wout
    transpose_round<<<tGrd, tBlk>>>(wq,  wcat + 0LL * DIMM * HD / 4 * 4, DIMM, HD, HD, 0, 0);
    transpose_round<<<tGrd, tBlk>>>(wk,  wcat + 1LL * HD * DIMM,         DIMM, HD, HD, 0, 0);
    transpose_round<<<tGrd, tBlk>>>(wv,  wcat + 2LL * HD * DIMM,         DIMM, HD, HD, 0, 0);
    transpose_round<<<tGrd, tBlk>>>(wvg, wcat + 3LL * HD * DIMM,         DIMM, HD, HD, 0, 0);
    transpose_round<<<tGrd, tBlk>>>(wout, (float*)pwoutT, HD, DIMM, DIMM, 0, 0);
    round_copy<<<TT * DIMM / 1024, 256>>>(x, (float*)pxr);

    // merged QKV + value-gate projection: C[2048][8192], sigmoid on vg slice
    gemm_tc<<<dim3(64, 16, 1), 256, SMEM_BYTES>>>(
        (float*)pxr, DIMM, 0, 0, wcat, DIMM, 0, 0,
        qkvg, QKVG_LD, 0, 0, DIMM, 16, bvg, 1.f);

    norm_rot2_kernel<<<8192, 256>>>(cope);

    // V transpose per batch: g_vt[b][c][n] = tf32(qkvg[b*NN+n][4096+c])
    transpose_round<<<dim3(64, 32, BB), tBlk>>>(
        qkvg + 4096, (float*)pvt, NN, HD, QKVG_LD,
        (long long)NN * QKVG_LD, (long long)HD * NN);

    // sim = 10 * Q @ K^T (causal tiles only)
    gemm_tc<<<dim3(8, 8, BB * HH), 256, SMEM_BYTES>>>(
        qkvg,        QKVG_LD, (long long)NN * QKVG_LD, DHH,
        qkvg + 2048, QKVG_LD, (long long)NN * QKVG_LD, DHH,
        (float*)psim, NN, 16LL * NN * NN, (long long)NN * NN,
        DHH, 2, nullptr, 10.0f);

    // fused mix-pre + CoPE softmax + mix-post
    score_fused<<<dim3(NN, BB), 256, SCORE_SMEM>>>(thp, tho);

    // out = attn2 @ V  (B = Vt [d][j]; triangular K; upper band of g_sim2 is zero)
    gemm_tc<<<dim3(1, 8, BB * HH), 256, SMEM_BYTES>>>(
        (float*)psim2, NN, 16LL * NN * NN, (long long)NN * NN,
        (float*)pvt, NN, (long long)HD * NN, (long long)DHH * NN,
        (float*)pouth, DHH, 16LL * NN * DHH, (long long)NN * DHH,
        NN, 4, nullptr, 1.f);

    hgate_kernel<<<TT, 512>>>(x, whg, bhg);
    gate_mul_kernel<<<(TT * HD) / 256, 256>>>();

    gemm_tc<<<dim3(16, 16, 1), 256, SMEM_BYTES>>>(
        (float*)pgated, HD, 0, 0, (float*)pwoutT, HD, 0, 0,
        out, DIMM, 0, 0, HD, 0, nullptr, 1.f);
}

// round 10
// speedup vs baseline: 1.0156x; 1.0156x over previous
#include <cuda_runtime.h>
#include <math.h>

#define BB   2
#define NN   1024
#define DIMM 2048
#define HH   16
#define DHH  128
#define TT   (BB*NN)    // 2048 tokens
#define HD   (HH*DHH)   // 2048
#define MAXP 16
#define NEGV -1e30f
#define QKVG_LD 8192

#define STAGES 3
#define ASTR   36                  // smem row stride (floats)
#define STAGE_A (128*ASTR)         // A tile floats per stage
#define SB_NF4 (STAGES*(128+128)*ASTR*4)   // 110592 B
#define SB_NF8 (STAGES*(128+256)*ASTR*4)   // 165888 B

// ---------------- scratch (device globals; zero-init, no allocs) ----------------
__device__ __align__(256) float g_qkvg[TT*QKVG_LD];    // q[0:2048) k[2048:4096) v[4096:6144) vg[6144:8192)
__device__ __align__(256) float g_vt[TT*HD];           // V transposed per batch: [b][c][n]
__device__ __align__(256) float g_sim [BB*HH*NN*NN];   // raw scores / attn (ping)
__device__ __align__(256) float g_sim2[BB*HH*NN*NN];   // mixed scores / mixed attn (pong)
__device__ __align__(256) float g_logits[BB*HH*NN*MAXP];
__device__ __align__(256) float g_outh[BB*HH*NN*DHH];
__device__ __align__(256) float g_hg[TT*HH];
__device__ __align__(256) float g_gated[TT*HD];
__device__ __align__(256) float g_cos[NN*DHH];
__device__ __align__(256) float g_sin[NN*DHH];
__device__ __align__(256) float g_xr[TT*DIMM];         // x rounded to tf32
__device__ __align__(256) float g_wcatT[4*DIMM*HD];    // [8192][2048]: wqT|wkT|wvT|wvgT
__device__ __align__(256) float g_woutT[HD*DIMM];

__device__ __forceinline__ float sigmoidf_(float x) { return 1.0f / (1.0f + expf(-x)); }

__device__ __forceinline__ unsigned f2tf(float x) {
    unsigned u; asm("cvt.rna.tf32.f32 %0, %1;" : "=r"(u) : "f"(x)); return u;
}
__device__ __forceinline__ float tf32r(float x) { return __uint_as_float(f2tf(x)); }

__device__ __forceinline__ void cpa16(float* dst, const float* src) {
    unsigned d = (unsigned)__cvta_generic_to_shared(dst);
    asm volatile("cp.async.cg.shared.global [%0], [%1], 16;" :: "r"(d), "l"(src));
}

__device__ __forceinline__ void ldsm4(unsigned& r0, unsigned& r1, unsigned& r2, unsigned& r3,
                                      const float* p) {
    unsigned a = (unsigned)__cvta_generic_to_shared(p);
    asm volatile("ldmatrix.sync.aligned.m8n8.x4.shared.b16 {%0,%1,%2,%3}, [%4];"
                 : "=r"(r0), "=r"(r1), "=r"(r2), "=r"(r3) : "r"(a));
}

#define MMA_TF32(cc, aa, bb)                                                     \
    asm volatile("mma.sync.aligned.m16n8k8.row.col.f32.tf32.tf32.f32 "           \
                 "{%0,%1,%2,%3},{%4,%5,%6,%7},{%8,%9},{%0,%1,%2,%3};"            \
                 : "+f"((cc)[0]), "+f"((cc)[1]), "+f"((cc)[2]), "+f"((cc)[3])    \
                 : "r"((aa)[0]), "r"((aa)[1]), "r"((aa)[2]), "r"((aa)[3]),       \
                   "r"((bb)[0]), "r"((bb)[1]))

// =====================================================================
// tf32 tensor-core GEMM. Operands MUST be pre-rounded to tf32 in gmem.
//   C[M,N] = scale * A[M,K] @ B^T  where B is stored [N][K] row-major.
// NF = n-frags per warp (4 -> 128x128 tile, 2 CTAs/SM; 8 -> 128x256, 1 CTA/SM)
// flags: 2 = causal block skip; 4 = triangular K bound (kmax=row0+128,
//        A upper band must be zero); 16 = sigmoid(acc+bias[col-6144]) for
//        col0 >= 6144 slice of merged projection.
// =====================================================================
template<int NF>
__global__ __launch_bounds__(256, (NF == 4 ? 2 : 1)) void gemm_tc(
    const float* __restrict__ A, int lda, long long sAb, long long sAh,
    const float* __restrict__ B, int ldb, long long sBb, long long sBh,
    float* __restrict__ C, int ldc, long long sCb, long long sCh,
    int K, int flags, const float* __restrict__ bias, float scale)
{
    constexpr int BN = NF * 32;            // block N tile
    constexpr int STAGE_B = BN * ASTR;     // B tile floats per stage
    if ((flags & 2) && blockIdx.x > blockIdx.y) return;
    int z = blockIdx.z, bz = z >> 4, hz = z & 15;
    const float* Ab = A + bz * sAb + hz * sAh;
    const float* Bb = B + bz * sBb + hz * sBh;
    float*       Cb = C + bz * sCb + hz * sCh;

    extern __shared__ float sm[];
    float* Asm = sm;
    float* Bsm = sm + STAGES * STAGE_A;

    const int tid = threadIdx.x, lane = tid & 31, wid = tid >> 5;
    const int wm = wid >> 2, wn = wid & 3;
    const int g = lane >> 2, tg = lane & 3;
    const int row0 = blockIdx.y * 128, col0 = blockIdx.x * BN;

    float c[4][NF][4];
#pragma unroll
    for (int mt = 0; mt < 4; mt++)
#pragma unroll
        for (int nt = 0; nt < NF; nt++)
#pragma unroll
            for (int e = 0; e < 4; e++) c[mt][nt][e] = 0.f;

    int kmax = K;
    if (flags & 4) { int t = row0 + 128; if (t < kmax) kmax = t; }
    const int niter = kmax >> 5;

    const int a_rl = (lane & 7) + ((lane >> 3) & 1) * 8;
    const int a_ko = (lane >> 4) * 4;
    const int b_rl = (lane & 7) + ((lane >> 4) & 1) * 8;
    const int b_ko = ((lane >> 3) & 1) * 4;
    const float* aF[4]; const float* bF[NF / 2];
#pragma unroll
    for (int mt = 0; mt < 4; mt++)
        aF[mt] = Asm + (wm * 64 + mt * 16 + a_rl) * ASTR + a_ko;
#pragma unroll
    for (int p = 0; p < NF / 2; p++)
        bF[p] = Bsm + (wn * (NF * 8) + p * 16 + b_rl) * ASTR + b_ko;

    auto load_stage = [&](int s, int k0) {
        float* as = Asm + s * STAGE_A;
        float* bs = Bsm + s * STAGE_B;
#pragma unroll
        for (int i = 0; i < 4; i++) {
            int chunk = i * 256 + tid;
            int r = chunk >> 3, seg = (chunk & 7) << 2;
            cpa16(as + r * ASTR + seg, Ab + (size_t)(row0 + r) * lda + k0 + seg);
        }
#pragma unroll
        for (int i = 0; i < NF; i++) {
            int chunk = i * 256 + tid;
            int r = chunk >> 3, seg = (chunk & 7) << 2;
            cpa16(bs + r * ASTR + seg, Bb + (size_t)(col0 + r) * ldb + k0 + seg);
        }
    };

    auto compute_stage = [&](int s) {
        const int offA = s * STAGE_A, offB = s * STAGE_B;
#pragma unroll
        for (int ks = 0; ks < 4; ks++) {
            const int kb = ks * 8;
            unsigned a[4][4], b[NF][2];
#pragma unroll
            for (int mt = 0; mt < 4; mt++)
                ldsm4(a[mt][0], a[mt][1], a[mt][2], a[mt][3], aF[mt] + offA + kb);
#pragma unroll
            for (int p = 0; p < NF / 2; p++) {
                unsigned t0, t1, t2, t3;
                ldsm4(t0, t1, t2, t3, bF[p] + offB + kb);
                b[2 * p][0] = t0; b[2 * p][1] = t1;
                b[2 * p + 1][0] = t2; b[2 * p + 1][1] = t3;
            }
#pragma unroll
            for (int mt = 0; mt < 4; mt++)
#pragma unroll
                for (int nt = 0; nt < NF; nt++)
                    MMA_TF32(c[mt][nt], a[mt], b[nt]);
        }
    };

#pragma unroll
    for (int s = 0; s < STAGES - 1; s++) {
        if (s < niter) load_stage(s, s * 32);
        asm volatile("cp.async.commit_group;");
    }
    for (int it = 0; it < niter; it++) {
        asm volatile("cp.async.wait_group %0;" :: "n"(STAGES - 2));
        __syncthreads();
        int nxt = it + STAGES - 1;
        if (nxt < niter) load_stage(nxt % STAGES, nxt * 32);
        asm volatile("cp.async.commit_group;");
        compute_stage(it % STAGES);
    }

#pragma unroll
    for (int mt = 0; mt < 4; mt++) {
        int r0 = row0 + wm * 64 + mt * 16 + g;
#pragma unroll
        for (int nt = 0; nt < NF; nt++) {
            int col = col0 + wn * (NF * 8) + nt * 8 + 2 * tg;
            float v0 = c[mt][nt][0] * scale, v1 = c[mt][nt][1] * scale;
            float v2 = c[mt][nt][2] * scale, v3 = c[mt][nt][3] * scale;
            if ((flags & 16) && col >= 6144) {
                float b0 = bias[col - 6144], b1 = bias[col + 1 - 6144];
                v0 = sigmoidf_(v0 + b0);  v1 = sigmoidf_(v1 + b1);
                v2 = sigmoidf_(v2 + b0);  v3 = sigmoidf_(v3 + b1);
            }
            float2 p0; p0.x = v0; p0.y = v1;
            float2 p1; p1.x = v2; p1.y = v3;
            *(float2*)(Cb + (size_t)r0 * ldc + col)       = p0;
            *(float2*)(Cb + (size_t)(r0 + 8) * ldc + col) = p1;
        }
    }
}

// ---------------- transpose + tf32 round: out[c][r] = tf32(in[r][c]) ----------------
__global__ void transpose_round(const float* __restrict__ in, float* __restrict__ out,
                                int rows, int cols, int ldin,
                                long long inz, long long outz) {
    __shared__ float t[32][33];
    const float* ip = in + blockIdx.z * inz;
    float* op = out + blockIdx.z * outz;
    int c0 = blockIdx.x * 32, r0 = blockIdx.y * 32;
    int tx = threadIdx.x, ty = threadIdx.y;   // 32 x 8
#pragma unroll
    for (int i = 0; i < 32; i += 8)
        t[ty + i][tx] = ip[(size_t)(r0 + ty + i) * ldin + c0 + tx];
    __syncthreads();
#pragma unroll
    for (int i = 0; i < 32; i += 8)
        op[(size_t)(c0 + ty + i) * rows + r0 + tx] = tf32r(t[tx][ty + i]);
}

// ---------------- 4-way weight transpose+round into g_wcatT ----------------
__global__ void transpose4_round(const float* __restrict__ w0, const float* __restrict__ w1,
                                 const float* __restrict__ w2, const float* __restrict__ w3) {
    __shared__ float t[32][33];
    const float* ip = (blockIdx.z == 0) ? w0 : (blockIdx.z == 1) ? w1
                    : (blockIdx.z == 2) ? w2 : w3;
    float* op = g_wcatT + (size_t)blockIdx.z * HD * DIMM;
    int c0 = blockIdx.x * 32, r0 = blockIdx.y * 32;
    int tx = threadIdx.x, ty = threadIdx.y;
#pragma unroll
    for (int i = 0; i < 32; i += 8)
        t[ty + i][tx] = ip[(size_t)(r0 + ty + i) * HD + c0 + tx];
    __syncthreads();
#pragma unroll
    for (int i = 0; i < 32; i += 8)
        op[(size_t)(c0 + ty + i) * DIMM + r0 + tx] = tf32r(t[tx][ty + i]);
}

// ---------------- tf32 round copy (x -> g_xr) ----------------
__global__ void round_copy(const float* __restrict__ in, float* __restrict__ out) {
    int i = (blockIdx.x * 256 + threadIdx.x) * 4;
    float4 v = *(const float4*)(in + i);
    v.x = tf32r(v.x); v.y = tf32r(v.y); v.z = tf32r(v.z); v.w = tf32r(v.w);
    *(float4*)(out + i) = v;
}

// ---------------- rope table ----------------
__global__ void rope_cs_kernel(const float* __restrict__ rf) {
    int idx = blockIdx.x * 256 + threadIdx.x;
    float f = rf[idx];
    g_cos[idx] = cosf(f);
    g_sin[idx] = sinf(f);
}

// ---------------- warp-per-vector L2-norm + rotary (+ CoPE logits for q) ----------
__global__ void norm_rot2_kernel(const float* __restrict__ cope) {
    int lane = threadIdx.x & 31;
    int w = blockIdx.x * 8 + (threadIdx.x >> 5);
    const int NV = TT * HH;
    int isK = (w >= NV) ? 1 : 0;
    int vec = isK ? (w - NV) : w;
    int token = vec >> 4, h = vec & 15;
    int n = token & (NN - 1), b = token >> 10;

    float* ptr = g_qkvg + (size_t)token * QKVG_LD + isK * 2048 + h * DHH + lane * 4;
    float4 v = *(float4*)ptr;
    float ss = v.x * v.x + v.y * v.y + v.z * v.z + v.w * v.w;
#pragma unroll
    for (int o = 16; o > 0; o >>= 1) ss += __shfl_xor_sync(0xffffffffu, ss, o);
    float inv = 1.0f / fmaxf(sqrtf(ss), 1e-12f);
    v.x *= inv; v.y *= inv; v.z *= inv; v.w *= inv;

    float4 cs = *(const float4*)(g_cos + n * DHH + lane * 4);
    float4 sn = *(const float4*)(g_sin + n * DHH + lane * 4);
    float4 o;
    o.x = v.x * cs.x - v.y * sn.x;
    o.y = v.y * cs.y + v.x * sn.y;
    o.z = v.z * cs.z - v.w * sn.z;
    o.w = v.w * cs.w + v.z * sn.w;
    float4 orr;
    orr.x = tf32r(o.x); orr.y = tf32r(o.y); orr.z = tf32r(o.z); orr.w = tf32r(o.w);
    *(float4*)ptr = orr;

    if (!isK) {
        float myv = 0.f;
#pragma unroll
        for (int p = 0; p < MAXP; p++) {
            float4 cp = *(const float4*)(cope + p * DHH + lane * 4);
            float pa = o.x * cp.x + o.y * cp.y + o.z * cp.z + o.w * cp.w;
#pragma unroll
            for (int off = 16; off > 0; off >>= 1)
                pa += __shfl_xor_sync(0xffffffffu, pa, off);
            if (lane == p) myv = pa;
        }
        if (lane < MAXP)
            g_logits[((size_t)(b * HH + h) * NN + n) * MAXP + lane] = myv;
    }
}

// ---------------- talking-heads mix (j<=i only); rnd=1 rounds stores to tf32 ------
__global__ void mix_heads_kernel(const float* __restrict__ th, int rnd) {
    int i = blockIdx.y, b = blockIdx.z;
    if ((int)(blockIdx.x * 256) > i) return;
    __shared__ float sth[256];
    sth[threadIdx.x] = th[threadIdx.x];
    __syncthreads();
    int j = blockIdx.x * 256 + threadIdx.x;
    if (j > i) return;
    size_t base = ((size_t)b * HH * NN + i) * NN + j;
    float vals[16];
#pragma unroll
    for (int g = 0; g < 16; g++) vals[g] = g_sim[base + (size_t)g * NN * NN];
#pragma unroll
    for (int h = 0; h < 16; h++) {
        float s = 0.f;
#pragma unroll
        for (int g = 0; g < 16; g++) s = fmaf(sth[h * 16 + g], vals[g], s);
        g_sim2[base + (size_t)h * NN * NN] = rnd ? tf32r(s) : s;
    }
}

// ---------------- CoPE + softmax per row (reads g_sim2, writes g_sim) ----------------
__global__ void cope_softmax_kernel() {
    int i = blockIdx.x, h = blockIdx.y, b = blockIdx.z;
    int tid = threadIdx.x;
    size_t rowbase = (((size_t)(b * HH + h)) * NN + i) * NN;

    __shared__ float lrow[MAXP];
    __shared__ float wsum[8], woff[8];
    __shared__ float s_total, s_m, s_sum;

    if (tid < MAXP)
        lrow[tid] = g_logits[(((size_t)(b * HH + h)) * NN + i) * MAXP + tid];

    int j0 = tid * 4;
    float v[4], g[4];
#pragma unroll
    for (int c = 0; c < 4; c++) {
        int j = j0 + c;
        if (j <= i) { v[c] = g_sim2[rowbase + j]; g[c] = sigmoidf_(v[c]); }
        else        { v[c] = NEGV;               g[c] = 0.f; }
    }
    float lp[4];
    lp[0] = 0.f; lp[1] = g[0]; lp[2] = lp[1] + g[1]; lp[3] = lp[2] + g[2];
    float tsum = lp[3] + g[3];

    unsigned lane = tid & 31, wid = tid >> 5;
    float incl = tsum;
#pragma unroll
    for (int o = 1; o < 32; o <<= 1) {
        float t = __shfl_up_sync(0xffffffffu, incl, o);
        if (lane >= o) incl += t;
    }
    if (lane == 31) wsum[wid] = incl;
    __syncthreads();
    if (tid == 0) {
        float run = 0.f;
        for (int w = 0; w < 8; w++) { woff[w] = run; run += wsum[w]; }
        s_total = run;
    }
    __syncthreads();
    float basex = (incl - tsum) + woff[wid];
    float total = s_total;

    float nv[4];
#pragma unroll
    for (int c = 0; c < 4; c++) {
        int j = j0 + c;
        if (j <= i) {
            float pos = total - (basex + lp[c]);
            pos = fminf(fmaxf(pos, 0.f), 15.0f);
            float pf = floorf(pos);
            float w  = pos - pf;
            int fi = (int)pf;
            int ci = (int)ceilf(pos);
            nv[c] = v[c] + lrow[ci] * w + lrow[fi] * (1.0f - w);
        } else nv[c] = NEGV;
    }
    float m = fmaxf(fmaxf(nv[0], nv[1]), fmaxf(nv[2], nv[3]));
#pragma unroll
    for (int o = 16; o > 0; o >>= 1) m = fmaxf(m, __shfl_xor_sync(0xffffffffu, m, o));
    if (lane == 0) wsum[wid] = m;
    __syncthreads();
    if (tid == 0) {
        float mm = wsum[0];
        for (int w = 1; w < 8; w++) mm = fmaxf(mm, wsum[w]);
        s_m = mm;
    }
    __syncthreads();
    m = s_m;
    float e[4]; float ls = 0.f;
#pragma unroll
    for (int c = 0; c < 4; c++) { e[c] = expf(nv[c] - m); ls += e[c]; }
#pragma unroll
    for (int o = 16; o > 0; o >>= 1) ls += __shfl_xor_sync(0xffffffffu, ls, o);
    if (lane == 0) woff[wid] = ls;
    __syncthreads();
    if (tid == 0) {
        float t = 0.f;
        for (int w = 0; w < 8; w++) t += woff[w];
        s_sum = t;
    }
    __syncthreads();
    float invs = 1.0f / s_sum;
#pragma unroll
    for (int c = 0; c < 4; c++) {
        int j = j0 + c;
        if (j <= i) g_sim[rowbase + j] = e[c] * invs;
    }
}

// ---------------- head gate ----------------
__global__ void hgate_kernel(const float* __restrict__ x, const float* __restrict__ wh,
                             const float* __restrict__ bh) {
    int token = blockIdx.x;
    __shared__ __align__(16) float sx[DIMM];
    int tid = threadIdx.x;
    *(float4*)&sx[tid * 4] = *(const float4*)&x[(size_t)token * DIMM + tid * 4];
    __syncthreads();
    int h = tid >> 5, lane = tid & 31;
    float s = 0.f;
    for (int e = lane; e < DIMM; e += 32) s = fmaf(sx[e], wh[e * HH + h], s);
#pragma unroll
    for (int o = 16; o > 0; o >>= 1) s += __shfl_xor_sync(0xffffffffu, s, o);
    if (lane == 0) g_hg[token * HH + h] = sigmoidf_(s + bh[h]);
}

// ---------------- apply gates, merge heads (tf32-rounded output) ----------------
__global__ void gate_mul_kernel() {
    int idx = blockIdx.x * 256 + threadIdx.x;
    int token = idx >> 11;
    int c = idx & 2047;
    int h = c >> 7, d = c & 127;
    int b = token >> 10, n = token & 1023;
    float o = g_outh[(((size_t)(b * HH + h)) * NN + n) * DHH + d];
    float vg = g_qkvg[(size_t)token * QKVG_LD + 6144 + c];
    g_gated[idx] = tf32r(o * g_hg[token * HH + h] * vg);
}

// ---------------- launch ----------------
extern "C" void kernel_launch(void* const* d_in, const int* in_sizes, int n_in,
                              void* d_out, int out_size) {
    const float* x    = (const float*)d_in[0];
    const float* rf   = (const float*)d_in[1];
    const float* wq   = (const float*)d_in[2];
    const float* wk   = (const float*)d_in[3];
    const float* wv   = (const float*)d_in[4];
    const float* cope = (const float*)d_in[5];
    const float* thp  = (const float*)d_in[6];
    const float* tho  = (const float*)d_in[7];
    const float* wvg  = (const float*)d_in[8];
    const float* bvg  = (const float*)d_in[9];
    const float* whg  = (const float*)d_in[10];
    const float* bhg  = (const float*)d_in[11];
    const float* wout = (const float*)d_in[12];
    float* out = (float*)d_out;

    cudaFuncSetAttribute(gemm_tc<4>, cudaFuncAttributeMaxDynamicSharedMemorySize, SB_NF4);
    cudaFuncSetAttribute(gemm_tc<8>, cudaFuncAttributeMaxDynamicSharedMemorySize, SB_NF8);

    void *pqkvg, *pvt, *psim, *psim2, *pouth, *pgated, *pxr, *pwcat, *pwoutT;
    cudaGetSymbolAddress(&pqkvg, g_qkvg);
    cudaGetSymbolAddress(&pvt, g_vt);
    cudaGetSymbolAddress(&psim, g_sim);
    cudaGetSymbolAddress(&psim2, g_sim2);
    cudaGetSymbolAddress(&pouth, g_outh);
    cudaGetSymbolAddress(&pgated, g_gated);
    cudaGetSymbolAddress(&pxr, g_xr);
    cudaGetSymbolAddress(&pwcat, g_wcatT);
    cudaGetSymbolAddress(&pwoutT, g_woutT);

    float* qkvg = (float*)pqkvg;
    float* wcat = (float*)pwcat;

    dim3 tBlk(32, 8);

    rope_cs_kernel<<<NN * DHH / 256, 256>>>(rf);

    // pre-pass: transpose+round the 4 projection weights (one launch) + wout, round x
    transpose4_round<<<dim3(64, 64, 4), tBlk>>>(wq, wk, wv, wvg);
    transpose_round<<<dim3(64, 64, 1), tBlk>>>(wout, (float*)pwoutT, HD, DIMM, DIMM, 0, 0);
    round_copy<<<TT * DIMM / 1024, 256>>>(x, (float*)pxr);

    // merged QKV + value-gate projection: C[2048][8192], wide tile, sigmoid on vg cols
    gemm_tc<8><<<dim3(32, 16, 1), 256, SB_NF8>>>(
        (float*)pxr, DIMM, 0, 0, wcat, DIMM, 0, 0,
        qkvg, QKVG_LD, 0, 0, DIMM, 16, bvg, 1.f);

    norm_rot2_kernel<<<8192, 256>>>(cope);

    // V transpose per batch: g_vt[b][c][n] = tf32(qkvg[b*NN+n][4096+c])
    transpose_round<<<dim3(64, 32, BB), tBlk>>>(
        qkvg + 4096, (float*)pvt, NN, HD, QKVG_LD,
        (long long)NN * QKVG_LD, (long long)HD * NN);

    // sim = 10 * Q @ K^T (causal tiles only)
    gemm_tc<4><<<dim3(8, 8, BB * HH), 256, SB_NF4>>>(
        qkvg,        QKVG_LD, (long long)NN * QKVG_LD, DHH,
        qkvg + 2048, QKVG_LD, (long long)NN * QKVG_LD, DHH,
        (float*)psim, NN, 16LL * NN * NN, (long long)NN * NN,
        DHH, 2, nullptr, 10.0f);

    // score chain: pre-mix -> CoPE softmax -> post-mix (tf32)
    mix_heads_kernel<<<dim3(4, NN, BB), 256>>>(thp, 0);   // g_sim -> g_sim2
    cope_softmax_kernel<<<dim3(NN, HH, BB), 256>>>();     // g_sim2 -> attn in g_sim
    mix_heads_kernel<<<dim3(4, NN, BB), 256>>>(tho, 1);   // g_sim -> g_sim2 (tf32)

    // out = attn2 @ V  (B = Vt [d][j]; triangular K; upper band of g_sim2 is zero)
    gemm_tc<4><<<dim3(1, 8, BB * HH), 256, SB_NF4>>>(
        (float*)psim2, NN, 16LL * NN * NN, (long long)NN * NN,
        (float*)pvt, NN, (long long)HD * NN, (long long)DHH * NN,
        (float*)pouth, DHH, 16LL * NN * DHH, (long long)NN * DHH,
        NN, 4, nullptr, 1.f);

    hgate_kernel<<<TT, 512>>>(x, whg, bhg);
    gate_mul_kernel<<<(TT * HD) / 256, 256>>>();

    // output projection: C[2048][2048], wide tile
    gemm_tc<8><<<dim3(8, 16, 1), 256, SB_NF8>>>(
        (float*)pgated, HD, 0, 0, (float*)pwoutT, HD, 0, 0,
        out, DIMM, 0, 0, HD, 0, nullptr, 1.f);
}

// round 16
// speedup vs baseline: 1.1110x; 1.0939x over previous
#include <cuda_runtime.h>
#include <math.h>

#define BB   2
#define NN   1024
#define DIMM 2048
#define HH   16
#define DHH  128
#define TT   (BB*NN)    // 2048 tokens
#define HD   (HH*DHH)   // 2048
#define MAXP 16
#define NEGV -1e30f
#define QKVG_LD 8192

#define STAGES 3
#define ASTR   36                  // smem row stride (floats)
#define STAGE_A (128*ASTR)
#define STAGE_B (128*ASTR)
#define SB_NF4 (STAGES*(128+128)*ASTR*4)   // 110592 B

// ---------------- scratch (device globals; zero-init, no allocs) ----------------
__device__ __align__(256) float g_qkvg[TT*QKVG_LD];    // q[0:2048) k[2048:4096) v[4096:6144) vg[6144:8192)
__device__ __align__(256) float g_vt[TT*HD];           // V transposed per batch: [b][c][n]
__device__ __align__(256) float g_sim [BB*HH*NN*NN];   // raw scores / attn (ping)
__device__ __align__(256) float g_sim2[BB*HH*NN*NN];   // mixed scores / mixed attn (pong)
__device__ __align__(256) float g_logits[BB*HH*NN*MAXP];
__device__ __align__(256) float g_outh[BB*HH*NN*DHH];
__device__ __align__(256) float g_hg[TT*HH];
__device__ __align__(256) float g_gated[TT*HD];
__device__ __align__(256) float g_cos[NN*DHH];
__device__ __align__(256) float g_sin[NN*DHH];
__device__ __align__(256) float g_xr[TT*DIMM];         // x rounded to tf32
__device__ __align__(256) float g_wcatT[4*DIMM*HD];    // [8192][2048]: wqT|wkT|wvT|wvgT
__device__ __align__(256) float g_woutT[HD*DIMM];

__device__ __forceinline__ float sigmoidf_(float x) { return 1.0f / (1.0f + expf(-x)); }

__device__ __forceinline__ unsigned f2tf(float x) {
    unsigned u; asm("cvt.rna.tf32.f32 %0, %1;" : "=r"(u) : "f"(x)); return u;
}
__device__ __forceinline__ float tf32r(float x) { return __uint_as_float(f2tf(x)); }

__device__ __forceinline__ void cpa16(float* dst, const float* src) {
    unsigned d = (unsigned)__cvta_generic_to_shared(dst);
    asm volatile("cp.async.cg.shared.global [%0], [%1], 16;" :: "r"(d), "l"(src));
}

__device__ __forceinline__ void ldsm4(unsigned& r0, unsigned& r1, unsigned& r2, unsigned& r3,
                                      const float* p) {
    unsigned a = (unsigned)__cvta_generic_to_shared(p);
    asm volatile("ldmatrix.sync.aligned.m8n8.x4.shared.b16 {%0,%1,%2,%3}, [%4];"
                 : "=r"(r0), "=r"(r1), "=r"(r2), "=r"(r3) : "r"(a));
}

#define MMA_TF32(cc, aa, bb)                                                     \
    asm volatile("mma.sync.aligned.m16n8k8.row.col.f32.tf32.tf32.f32 "           \
                 "{%0,%1,%2,%3},{%4,%5,%6,%7},{%8,%9},{%0,%1,%2,%3};"            \
                 : "+f"((cc)[0]), "+f"((cc)[1]), "+f"((cc)[2]), "+f"((cc)[3])    \
                 : "r"((aa)[0]), "r"((aa)[1]), "r"((aa)[2]), "r"((aa)[3]),       \
                   "r"((bb)[0]), "r"((bb)[1]))

// =====================================================================
// mma.sync tf32 GEMM. Operands pre-rounded to tf32 in gmem.
//   C[M,N] = scale * A[M,K] @ B^T  where B is stored [N][K] row-major.
// Tile 128x128, 2 CTAs/SM, 3-stage cp.async, ldmatrix fragments.
// flags: 2 = causal block skip; 4 = triangular K bound (kmax=row0+128,
//        A upper band must be zero); 16 = sigmoid(acc+bias[col-6144]) for
//        cols >= 6144 (merged-projection vgate slice);
//        32 = L2-friendly block swizzle (16-column stripes).
// =====================================================================
__global__ __launch_bounds__(256, 2) void gemm_tc(
    const float* __restrict__ A, int lda, long long sAb, long long sAh,
    const float* __restrict__ B, int ldb, long long sBb, long long sBh,
    float* __restrict__ C, int ldc, long long sCb, long long sCh,
    int K, int flags, const float* __restrict__ bias, float scale)
{
    int bx = blockIdx.x, by = blockIdx.y;
    if (flags & 32) {
        // column-stripe swizzle: consecutive blocks sweep 16 columns x all rows
        int bid = by * gridDim.x + bx;
        int per = 16 * gridDim.y;
        int cg = bid / per, rem = bid - cg * per;
        by = rem >> 4;
        bx = cg * 16 + (rem & 15);
    }
    if ((flags & 2) && bx > by) return;
    int z = blockIdx.z, bz = z >> 4, hz = z & 15;
    const float* Ab = A + bz * sAb + hz * sAh;
    const float* Bb = B + bz * sBb + hz * sBh;
    float*       Cb = C + bz * sCb + hz * sCh;

    extern __shared__ float sm[];
    float* Asm = sm;
    float* Bsm = sm + STAGES * STAGE_A;

    const int tid = threadIdx.x, lane = tid & 31, wid = tid >> 5;
    const int wm = wid >> 2, wn = wid & 3;
    const int g = lane >> 2, tg = lane & 3;
    const int row0 = by * 128, col0 = bx * 128;

    float c[4][4][4];
#pragma unroll
    for (int mt = 0; mt < 4; mt++)
#pragma unroll
        for (int nt = 0; nt < 4; nt++)
#pragma unroll
            for (int e = 0; e < 4; e++) c[mt][nt][e] = 0.f;

    int kmax = K;
    if (flags & 4) { int t = row0 + 128; if (t < kmax) kmax = t; }
    const int niter = kmax >> 5;

    const int a_rl = (lane & 7) + ((lane >> 3) & 1) * 8;
    const int a_ko = (lane >> 4) * 4;
    const int b_rl = (lane & 7) + ((lane >> 4) & 1) * 8;
    const int b_ko = ((lane >> 3) & 1) * 4;
    const float* aF[4]; const float* bF[2];
#pragma unroll
    for (int mt = 0; mt < 4; mt++)
        aF[mt] = Asm + (wm * 64 + mt * 16 + a_rl) * ASTR + a_ko;
#pragma unroll
    for (int p = 0; p < 2; p++)
        bF[p] = Bsm + (wn * 32 + p * 16 + b_rl) * ASTR + b_ko;

    auto load_stage = [&](int s, int k0) {
        float* as = Asm + s * STAGE_A;
        float* bs = Bsm + s * STAGE_B;
#pragma unroll
        for (int i = 0; i < 4; i++) {
            int chunk = i * 256 + tid;
            int r = chunk >> 3, seg = (chunk & 7) << 2;
            cpa16(as + r * ASTR + seg, Ab + (size_t)(row0 + r) * lda + k0 + seg);
            cpa16(bs + r * ASTR + seg, Bb + (size_t)(col0 + r) * ldb + k0 + seg);
        }
    };

    auto compute_stage = [&](int s) {
        const int offA = s * STAGE_A, offB = s * STAGE_B;
#pragma unroll
        for (int ks = 0; ks < 4; ks++) {
            const int kb = ks * 8;
            unsigned a[4][4], b[4][2];
#pragma unroll
            for (int mt = 0; mt < 4; mt++)
                ldsm4(a[mt][0], a[mt][1], a[mt][2], a[mt][3], aF[mt] + offA + kb);
#pragma unroll
            for (int p = 0; p < 2; p++) {
                unsigned t0, t1, t2, t3;
                ldsm4(t0, t1, t2, t3, bF[p] + offB + kb);
                b[2 * p][0] = t0; b[2 * p][1] = t1;
                b[2 * p + 1][0] = t2; b[2 * p + 1][1] = t3;
            }
#pragma unroll
            for (int mt = 0; mt < 4; mt++)
#pragma unroll
                for (int nt = 0; nt < 4; nt++)
                    MMA_TF32(c[mt][nt], a[mt], b[nt]);
        }
    };

#pragma unroll
    for (int s = 0; s < STAGES - 1; s++) {
        if (s < niter) load_stage(s, s * 32);
        asm volatile("cp.async.commit_group;");
    }
    for (int it = 0; it < niter; it++) {
        asm volatile("cp.async.wait_group %0;" :: "n"(STAGES - 2));
        __syncthreads();
        int nxt = it + STAGES - 1;
        if (nxt < niter) load_stage(nxt % STAGES, nxt * 32);
        asm volatile("cp.async.commit_group;");
        compute_stage(it % STAGES);
    }

#pragma unroll
    for (int mt = 0; mt < 4; mt++) {
        int r0 = row0 + wm * 64 + mt * 16 + g;
#pragma unroll
        for (int nt = 0; nt < 4; nt++) {
            int col = col0 + wn * 32 + nt * 8 + 2 * tg;
            float v0 = c[mt][nt][0] * scale, v1 = c[mt][nt][1] * scale;
            float v2 = c[mt][nt][2] * scale, v3 = c[mt][nt][3] * scale;
            if ((flags & 16) && col >= 6144) {
                float b0 = bias[col - 6144], b1 = bias[col + 1 - 6144];
                v0 = sigmoidf_(v0 + b0);  v1 = sigmoidf_(v1 + b1);
                v2 = sigmoidf_(v2 + b0);  v3 = sigmoidf_(v3 + b1);
            }
            float2 p0; p0.x = v0; p0.y = v1;
            float2 p1; p1.x = v2; p1.y = v3;
            *(float2*)(Cb + (size_t)r0 * ldc + col)       = p0;
            *(float2*)(Cb + (size_t)(r0 + 8) * ldc + col) = p1;
        }
    }
}

// ---------------- transpose + tf32 round: out[c][r] = tf32(in[r][c]) ----------------
__global__ void transpose_round(const float* __restrict__ in, float* __restrict__ out,
                                int rows, int cols, int ldin,
                                long long inz, long long outz) {
    __shared__ float t[32][33];
    const float* ip = in + blockIdx.z * inz;
    float* op = out + blockIdx.z * outz;
    int c0 = blockIdx.x * 32, r0 = blockIdx.y * 32;
    int tx = threadIdx.x, ty = threadIdx.y;   // 32 x 8
#pragma unroll
    for (int i = 0; i < 32; i += 8)
        t[ty + i][tx] = ip[(size_t)(r0 + ty + i) * ldin + c0 + tx];
    __syncthreads();
#pragma unroll
    for (int i = 0; i < 32; i += 8)
        op[(size_t)(c0 + ty + i) * rows + r0 + tx] = tf32r(t[tx][ty + i]);
}

// ---------------- 4-way weight transpose+round into g_wcatT ----------------
__global__ void transpose4_round(const float* __restrict__ w0, const float* __restrict__ w1,
                                 const float* __restrict__ w2, const float* __restrict__ w3) {
    __shared__ float t[32][33];
    const float* ip = (blockIdx.z == 0) ? w0 : (blockIdx.z == 1) ? w1
                    : (blockIdx.z == 2) ? w2 : w3;
    float* op = g_wcatT + (size_t)blockIdx.z * HD * DIMM;
    int c0 = blockIdx.x * 32, r0 = blockIdx.y * 32;
    int tx = threadIdx.x, ty = threadIdx.y;
#pragma unroll
    for (int i = 0; i < 32; i += 8)
        t[ty + i][tx] = ip[(size_t)(r0 + ty + i) * HD + c0 + tx];
    __syncthreads();
#pragma unroll
    for (int i = 0; i < 32; i += 8)
        op[(size_t)(c0 + ty + i) * DIMM + r0 + tx] = tf32r(t[tx][ty + i]);
}

// ---------------- tf32 round copy (x -> g_xr) ----------------
__global__ void round_copy(const float* __restrict__ in, float* __restrict__ out) {
    int i = (blockIdx.x * 256 + threadIdx.x) * 4;
    float4 v = *(const float4*)(in + i);
    v.x = tf32r(v.x); v.y = tf32r(v.y); v.z = tf32r(v.z); v.w = tf32r(v.w);
    *(float4*)(out + i) = v;
}

// ---------------- rope table ----------------
__global__ void rope_cs_kernel(const float* __restrict__ rf) {
    int idx = blockIdx.x * 256 + threadIdx.x;
    float f = rf[idx];
    g_cos[idx] = cosf(f);
    g_sin[idx] = sinf(f);
}

// ---------------- warp-per-vector L2-norm + rotary (+ CoPE logits for q) ----------
__global__ void norm_rot2_kernel(const float* __restrict__ cope) {
    int lane = threadIdx.x & 31;
    int w = blockIdx.x * 8 + (threadIdx.x >> 5);
    const int NV = TT * HH;
    int isK = (w >= NV) ? 1 : 0;
    int vec = isK ? (w - NV) : w;
    int token = vec >> 4, h = vec & 15;
    int n = token & (NN - 1), b = token >> 10;

    float* ptr = g_qkvg + (size_t)token * QKVG_LD + isK * 2048 + h * DHH + lane * 4;
    float4 v = *(float4*)ptr;
    float ss = v.x * v.x + v.y * v.y + v.z * v.z + v.w * v.w;
#pragma unroll
    for (int o = 16; o > 0; o >>= 1) ss += __shfl_xor_sync(0xffffffffu, ss, o);
    float inv = 1.0f / fmaxf(sqrtf(ss), 1e-12f);
    v.x *= inv; v.y *= inv; v.z *= inv; v.w *= inv;

    float4 cs = *(const float4*)(g_cos + n * DHH + lane * 4);
    float4 sn = *(const float4*)(g_sin + n * DHH + lane * 4);
    float4 o;
    o.x = v.x * cs.x - v.y * sn.x;
    o.y = v.y * cs.y + v.x * sn.y;
    o.z = v.z * cs.z - v.w * sn.z;
    o.w = v.w * cs.w + v.z * sn.w;
    float4 orr;
    orr.x = tf32r(o.x); orr.y = tf32r(o.y); orr.z = tf32r(o.z); orr.w = tf32r(o.w);
    *(float4*)ptr = orr;

    if (!isK) {
        float myv = 0.f;
#pragma unroll
        for (int p = 0; p < MAXP; p++) {
            float4 cp = *(const float4*)(cope + p * DHH + lane * 4);
            float pa = o.x * cp.x + o.y * cp.y + o.z * cp.z + o.w * cp.w;
#pragma unroll
            for (int off = 16; off > 0; off >>= 1)
                pa += __shfl_xor_sync(0xffffffffu, pa, off);
            if (lane == p) myv = pa;
        }
        if (lane < MAXP)
            g_logits[((size_t)(b * HH + h) * NN + n) * MAXP + lane] = myv;
    }
}

// ---------------- talking-heads mix (j<=i only); rnd=1 rounds stores to tf32 ------
__global__ void mix_heads_kernel(const float* __restrict__ th, int rnd) {
    int i = blockIdx.y, b = blockIdx.z;
    if ((int)(blockIdx.x * 256) > i) return;
    __shared__ float sth[256];
    sth[threadIdx.x] = th[threadIdx.x];
    __syncthreads();
    int j = blockIdx.x * 256 + threadIdx.x;
    if (j > i) return;
    size_t base = ((size_t)b * HH * NN + i) * NN + j;
    float vals[16];
#pragma unroll
    for (int g = 0; g < 16; g++) vals[g] = g_sim[base + (size_t)g * NN * NN];
#pragma unroll
    for (int h = 0; h < 16; h++) {
        float s = 0.f;
#pragma unroll
        for (int g = 0; g < 16; g++) s = fmaf(sth[h * 16 + g], vals[g], s);
        g_sim2[base + (size_t)h * NN * NN] = rnd ? tf32r(s) : s;
    }
}

// ---------------- CoPE + softmax per row (reads g_sim2, writes g_sim) ----------------
__global__ void cope_softmax_kernel() {
    int i = blockIdx.x, h = blockIdx.y, b = blockIdx.z;
    int tid = threadIdx.x;
    size_t rowbase = (((size_t)(b * HH + h)) * NN + i) * NN;

    __shared__ float lrow[MAXP];
    __shared__ float wsum[8], woff[8];
    __shared__ float s_total, s_m, s_sum;

    if (tid < MAXP)
        lrow[tid] = g_logits[(((size_t)(b * HH + h)) * NN + i) * MAXP + tid];

    int j0 = tid * 4;
    float v[4], g[4];
#pragma unroll
    for (int c = 0; c < 4; c++) {
        int j = j0 + c;
        if (j <= i) { v[c] = g_sim2[rowbase + j]; g[c] = sigmoidf_(v[c]); }
        else        { v[c] = NEGV;               g[c] = 0.f; }
    }
    float lp[4];
    lp[0] = 0.f; lp[1] = g[0]; lp[2] = lp[1] + g[1]; lp[3] = lp[2] + g[2];
    float tsum = lp[3] + g[3];

    unsigned lane = tid & 31, wid = tid >> 5;
    float incl = tsum;
#pragma unroll
    for (int o = 1; o < 32; o <<= 1) {
        float t = __shfl_up_sync(0xffffffffu, incl, o);
        if (lane >= o) incl += t;
    }
    if (lane == 31) wsum[wid] = incl;
    __syncthreads();
    if (tid == 0) {
        float run = 0.f;
        for (int w = 0; w < 8; w++) { woff[w] = run; run += wsum[w]; }
        s_total = run;
    }
    __syncthreads();
    float basex = (incl - tsum) + woff[wid];
    float total = s_total;

    float nv[4];
#pragma unroll
    for (int c = 0; c < 4; c++) {
        int j = j0 + c;
        if (j <= i) {
            float pos = total - (basex + lp[c]);
            pos = fminf(fmaxf(pos, 0.f), 15.0f);
            float pf = floorf(pos);
            float w  = pos - pf;
            int fi = (int)pf;
            int ci = (int)ceilf(pos);
            nv[c] = v[c] + lrow[ci] * w + lrow[fi] * (1.0f - w);
        } else nv[c] = NEGV;
    }
    float m = fmaxf(fmaxf(nv[0], nv[1]), fmaxf(nv[2], nv[3]));
#pragma unroll
    for (int o = 16; o > 0; o >>= 1) m = fmaxf(m, __shfl_xor_sync(0xffffffffu, m, o));
    if (lane == 0) wsum[wid] = m;
    __syncthreads();
    if (tid == 0) {
        float mm = wsum[0];
        for (int w = 1; w < 8; w++) mm = fmaxf(mm, wsum[w]);
        s_m = mm;
    }
    __syncthreads();
    m = s_m;
    float e[4]; float ls = 0.f;
#pragma unroll
    for (int c = 0; c < 4; c++) { e[c] = expf(nv[c] - m); ls += e[c]; }
#pragma unroll
    for (int o = 16; o > 0; o >>= 1) ls += __shfl_xor_sync(0xffffffffu, ls, o);
    if (lane == 0) woff[wid] = ls;
    __syncthreads();
    if (tid == 0) {
        float t = 0.f;
        for (int w = 0; w < 8; w++) t += woff[w];
        s_sum = t;
    }
    __syncthreads();
    float invs = 1.0f / s_sum;
#pragma unroll
    for (int c = 0; c < 4; c++) {
        int j = j0 + c;
        if (j <= i) g_sim[rowbase + j] = e[c] * invs;
    }
}

// ---------------- head gate ----------------
__global__ void hgate_kernel(const float* __restrict__ x, const float* __restrict__ wh,
                             const float* __restrict__ bh) {
    int token = blockIdx.x;
    __shared__ __align__(16) float sx[DIMM];
    int tid = threadIdx.x;
    *(float4*)&sx[tid * 4] = *(const float4*)&x[(size_t)token * DIMM + tid * 4];
    __syncthreads();
    int h = tid >> 5, lane = tid & 31;
    float s = 0.f;
    for (int e = lane; e < DIMM; e += 32) s = fmaf(sx[e], wh[e * HH + h], s);
#pragma unroll
    for (int o = 16; o > 0; o >>= 1) s += __shfl_xor_sync(0xffffffffu, s, o);
    if (lane == 0) g_hg[token * HH + h] = sigmoidf_(s + bh[h]);
}

// ---------------- apply gates, merge heads (tf32-rounded output) ----------------
__global__ void gate_mul_kernel() {
    int idx = blockIdx.x * 256 + threadIdx.x;
    int token = idx >> 11;
    int c = idx & 2047;
    int h = c >> 7, d = c & 127;
    int b = token >> 10, n = token & 1023;
    float o = g_outh[(((size_t)(b * HH + h)) * NN + n) * DHH + d];
    float vg = g_qkvg[(size_t)token * QKVG_LD + 6144 + c];
    g_gated[idx] = tf32r(o * g_hg[token * HH + h] * vg);
}

// ---------------- launch ----------------
extern "C" void kernel_launch(void* const* d_in, const int* in_sizes, int n_in,
                              void* d_out, int out_size) {
    const float* x    = (const float*)d_in[0];
    const float* rf   = (const float*)d_in[1];
    const float* wq   = (const float*)d_in[2];
    const float* wk   = (const float*)d_in[3];
    const float* wv   = (const float*)d_in[4];
    const float* cope = (const float*)d_in[5];
    const float* thp  = (const float*)d_in[6];
    const float* tho  = (const float*)d_in[7];
    const float* wvg  = (const float*)d_in[8];
    const float* bvg  = (const float*)d_in[9];
    const float* whg  = (const float*)d_in[10];
    const float* bhg  = (const float*)d_in[11];
    const float* wout = (const float*)d_in[12];
    float* out = (float*)d_out;

    cudaFuncSetAttribute(gemm_tc, cudaFuncAttributeMaxDynamicSharedMemorySize, SB_NF4);

    void *pqkvg, *pvt, *psim, *psim2, *pouth, *pgated, *pxr, *pwcat, *pwoutT;
    cudaGetSymbolAddress(&pqkvg, g_qkvg);
    cudaGetSymbolAddress(&pvt, g_vt);
    cudaGetSymbolAddress(&psim, g_sim);
    cudaGetSymbolAddress(&psim2, g_sim2);
    cudaGetSymbolAddress(&pouth, g_outh);
    cudaGetSymbolAddress(&pgated, g_gated);
    cudaGetSymbolAddress(&pxr, g_xr);
    cudaGetSymbolAddress(&pwcat, g_wcatT);
    cudaGetSymbolAddress(&pwoutT, g_woutT);

    float* qkvg = (float*)pqkvg;
    float* wcat = (float*)pwcat;

    dim3 tBlk(32, 8);

    rope_cs_kernel<<<NN * DHH / 256, 256>>>(rf);

    // pre-pass: transpose+round 4 projection weights (one launch) + wout, round x
    transpose4_round<<<dim3(64, 64, 4), tBlk>>>(wq, wk, wv, wvg);
    transpose_round<<<dim3(64, 64, 1), tBlk>>>(wout, (float*)pwoutT, HD, DIMM, DIMM, 0, 0);
    round_copy<<<TT * DIMM / 1024, 256>>>(x, (float*)pxr);

    // merged QKV + value-gate projection: C[2048][8192], swizzled block order,
    // sigmoid epilogue on vg cols
    gemm_tc<<<dim3(64, 16, 1), 256, SB_NF4>>>(
        (float*)pxr, DIMM, 0, 0, wcat, DIMM, 0, 0,
        qkvg, QKVG_LD, 0, 0, DIMM, 16 | 32, bvg, 1.f);

    norm_rot2_kernel<<<8192, 256>>>(cope);

    // V transpose per batch: g_vt[b][c][n] = tf32(qkvg[b*NN+n][4096+c])
    transpose_round<<<dim3(64, 32, BB), tBlk>>>(
        qkvg + 4096, (float*)pvt, NN, HD, QKVG_LD,
        (long long)NN * QKVG_LD, (long long)HD * NN);

    // sim = 10 * Q @ K^T (causal tiles only)
    gemm_tc<<<dim3(8, 8, BB * HH), 256, SB_NF4>>>(
        qkvg,        QKVG_LD, (long long)NN * QKVG_LD, DHH,
        qkvg + 2048, QKVG_LD, (long long)NN * QKVG_LD, DHH,
        (float*)psim, NN, 16LL * NN * NN, (long long)NN * NN,
        DHH, 2, nullptr, 10.0f);

    // score chain: pre-mix -> CoPE softmax -> post-mix (tf32)
    mix_heads_kernel<<<dim3(4, NN, BB), 256>>>(thp, 0);
    cope_softmax_kernel<<<dim3(NN, HH, BB), 256>>>();
    mix_heads_kernel<<<dim3(4, NN, BB), 256>>>(tho, 1);

    // out = attn2 @ V  (triangular K; upper band of g_sim2 is zero)
    gemm_tc<<<dim3(1, 8, BB * HH), 256, SB_NF4>>>(
        (float*)psim2, NN, 16LL * NN * NN, (long long)NN * NN,
        (float*)pvt, NN, (long long)HD * NN, (long long)DHH * NN,
        (float*)pouth, DHH, 16LL * NN * DHH, (long long)NN * DHH,
        NN, 4, nullptr, 1.f);

    hgate_kernel<<<TT, 512>>>(x, whg, bhg);
    gate_mul_kernel<<<(TT * HD) / 256, 256>>>();

    // output projection: C[2048][2048]
    gemm_tc<<<dim3(16, 16, 1), 256, SB_NF4>>>(
        (float*)pgated, HD, 0, 0, (float*)pwoutT, HD, 0, 0,
        out, DIMM, 0, 0, HD, 0, nullptr, 1.f);
}